// round 5
// baseline (speedup 1.0000x reference)
#include <cuda_runtime.h>

#define D_DIM 1024
#define L_DIM 24
#define TPB   256
#define CPT   4           // columns per thread: 1024 / 256
#define EPSV  1e-8f

// shared layout (floats): W_enc [24*1024] | red [8*32] | corr [24] | scal [8]
#define SM_WE    0
#define SM_RED   (L_DIM * D_DIM)
#define SM_CORR  (SM_RED + 8 * 32)
#define SM_SCAL  (SM_CORR + 32)
#define SM_FLOATS (SM_SCAL + 8)
#define SM_BYTES (SM_FLOATS * 4)

__global__ __launch_bounds__(TPB, 1)
void leech_fused_kernel(const float* __restrict__ data,
                        const float* __restrict__ W_enc,
                        const float* __restrict__ b_enc,
                        const float* __restrict__ W_dec,
                        const float* __restrict__ b_dec,
                        const float* __restrict__ ecs_p,
                        const float* __restrict__ ep_p,
                        float* __restrict__ out,
                        int n_rows)
{
    extern __shared__ float smem[];
    float* sWe   = smem + SM_WE;
    float* sRed  = smem + SM_RED;
    float* sCorr = smem + SM_CORR;
    float* sScal = smem + SM_SCAL;

    const int t    = threadIdx.x;
    const int wid  = t >> 5;
    const int lane = t & 31;
    const int c0   = t * CPT;

    // ---- one-time prologue: stage W_enc to shared, W_dec slice to registers ----
    {
        const float4* src = reinterpret_cast<const float4*>(W_enc);
        float4* dst = reinterpret_cast<float4*>(sWe);
        #pragma unroll
        for (int i = 0; i < (L_DIM * D_DIM / 4) / TPB; ++i)
            dst[i * TPB + t] = src[i * TPB + t];
    }

    float wd[CPT][L_DIM];            // W_dec[c0+j][l] — 96 registers, reused every row
    #pragma unroll
    for (int j = 0; j < CPT; ++j) {
        #pragma unroll
        for (int l = 0; l < L_DIM; l += 4) {
            float4 v = *reinterpret_cast<const float4*>(&W_dec[(c0 + j) * L_DIM + l]);
            wd[j][l + 0] = v.x; wd[j][l + 1] = v.y;
            wd[j][l + 2] = v.z; wd[j][l + 3] = v.w;
        }
    }
    const float4 bd  = *reinterpret_cast<const float4*>(&b_dec[c0]);
    const float  ecs = ecs_p[0];
    const float  ep  = ep_p[0];
    float benc = 0.0f;
    if (wid == 0 && lane < L_DIM) benc = b_enc[lane];

    __syncthreads();

    int row = blockIdx.x;
    const int stride = gridDim.x;

    float4 dv = make_float4(0.f, 0.f, 0.f, 0.f);
    if (row < n_rows)
        dv = *reinterpret_cast<const float4*>(&data[(size_t)row * D_DIM + c0]);

    for (; row < n_rows; row += stride) {
        // ---- prefetch next row's data early (hides DRAM latency behind row body) ----
        const int nrow = row + stride;
        float4 dnext = make_float4(0.f, 0.f, 0.f, 0.f);
        if (nrow < n_rows)
            dnext = *reinterpret_cast<const float4*>(&data[(size_t)nrow * D_DIM + c0]);

        // ---- encode: per-thread partial proj[24] and sum-of-squares ----
        float ss = dv.x * dv.x + dv.y * dv.y + dv.z * dv.z + dv.w * dv.w;
        float acc[L_DIM];
        #pragma unroll
        for (int l = 0; l < L_DIM; ++l) {
            float4 w = *reinterpret_cast<const float4*>(&sWe[l * D_DIM + c0]);
            float a = dv.x * w.x;
            a = fmaf(dv.y, w.y, a);
            a = fmaf(dv.z, w.z, a);
            a = fmaf(dv.w, w.w, a);
            acc[l] = a;
        }

        // ---- in-warp butterfly reduce of 25 values ----
        #pragma unroll
        for (int off = 16; off > 0; off >>= 1) {
            ss += __shfl_xor_sync(0xffffffffu, ss, off);
            #pragma unroll
            for (int l = 0; l < L_DIM; ++l)
                acc[l] += __shfl_xor_sync(0xffffffffu, acc[l], off);
        }
        if (lane == 0) {
            #pragma unroll
            for (int l = 0; l < L_DIM; ++l)
                sRed[wid * 32 + l] = acc[l];
            sRed[wid * 32 + L_DIM] = ss;
        }
        __syncthreads();                      // barrier 1

        // ---- warp 0: cross-warp reduce, quantize, lattice math ----
        if (wid == 0) {
            float s = 0.0f;
            if (lane <= L_DIM) {
                #pragma unroll
                for (int w = 0; w < TPB / 32; ++w)
                    s += sRed[w * 32 + lane];
            }
            const float sumsq = __shfl_sync(0xffffffffu, s, L_DIM);  // lane 24 slot
            const float in_e  = sqrtf(sumsq);

            float lp = 0.0f;
            if (lane < L_DIM) {
                const float proj = s + benc;
                lp = rintf(proj / ecs) * ecs;   // exact div + half-even round == jnp.round
            }
            float q = lp * lp;
            #pragma unroll
            for (int off = 16; off > 0; off >>= 1)
                q += __shfl_xor_sync(0xffffffffu, q, off);
            const float out_e = sqrtf(q);

            const float s1  = in_e / (out_e + EPSV) * ep;
            const float lat = lp * s1;
            const float cor = (fabsf(lat) > ecs) ? lat : 0.0f;
            if (lane < L_DIM) sCorr[lane] = cor;
            if (lane == 0)    sScal[0] = fabsf(s1) * out_e;   // in_e2 = ||lattice||
        }
        __syncthreads();                      // barrier 2

        // ---- decode: res = W_dec · corrected + b_dec (weights in registers) ----
        float cr[L_DIM];
        #pragma unroll
        for (int l = 0; l < L_DIM; ++l) cr[l] = sCorr[l];   // broadcast LDS

        float r0 = bd.x, r1 = bd.y, r2 = bd.z, r3 = bd.w;
        #pragma unroll
        for (int l = 0; l < L_DIM; ++l) {
            r0 = fmaf(cr[l], wd[0][l], r0);
            r1 = fmaf(cr[l], wd[1][l], r1);
            r2 = fmaf(cr[l], wd[2][l], r2);
            r3 = fmaf(cr[l], wd[3][l], r3);
        }

        // ---- out_e2 reduction ----
        float oss = r0 * r0 + r1 * r1 + r2 * r2 + r3 * r3;
        #pragma unroll
        for (int off = 16; off > 0; off >>= 1)
            oss += __shfl_xor_sync(0xffffffffu, oss, off);
        if (lane == 0) sRed[wid * 32 + 31] = oss;   // slot 31 is unused by encode
        __syncthreads();                      // barrier 3

        float oe2 = 0.0f;
        #pragma unroll
        for (int w = 0; w < TPB / 32; ++w)
            oe2 += sRed[w * 32 + 31];

        const float in_e2 = sScal[0];
        const float s2 = in_e2 / (sqrtf(oe2) + EPSV) * ep;

        float4 o;
        o.x = r0 * s2; o.y = r1 * s2; o.z = r2 * s2; o.w = r3 * s2;
        *reinterpret_cast<float4*>(&out[(size_t)row * D_DIM + c0]) = o;

        dv = dnext;
    }
}

extern "C" void kernel_launch(void* const* d_in, const int* in_sizes, int n_in,
                              void* d_out, int out_size)
{
    const float* data  = (const float*)d_in[0];
    const float* W_enc = (const float*)d_in[1];
    const float* b_enc = (const float*)d_in[2];
    const float* W_dec = (const float*)d_in[3];
    const float* b_dec = (const float*)d_in[4];
    const float* ecs   = (const float*)d_in[5];
    const float* ep    = (const float*)d_in[6];
    float* out = (float*)d_out;

    const int n_rows = in_sizes[0] / D_DIM;   // 32768

    // grid = SM count (persistent CTAs; static row partition, so grid must not
    // exceed the number of concurrently-resident CTAs). Query is not a stream
    // op, safe under graph capture; no caching so kernel_launch stays stateless.
    int dev = 0;
    cudaGetDevice(&dev);
    int sms = 0;
    cudaDeviceGetAttribute(&sms, cudaDevAttrMultiProcessorCount, dev);
    if (sms <= 0) sms = 148;

    cudaFuncSetAttribute(leech_fused_kernel,
                         cudaFuncAttributeMaxDynamicSharedMemorySize, SM_BYTES);

    leech_fused_kernel<<<sms, TPB, SM_BYTES>>>(data, W_enc, b_enc, W_dec, b_dec,
                                               ecs, ep, out, n_rows);
}

// round 6
// speedup vs baseline: 1.7338x; 1.7338x over previous
#include <cuda_runtime.h>

#define D_DIM 1024
#define L_DIM 24
#define TPB   256
#define CPT   4           // columns per thread: 1024 / 256
#define EPSV  1e-8f
#define FULL  0xffffffffu

__global__ __launch_bounds__(TPB, 1)
void leech_fused_kernel(const float* __restrict__ data,
                        const float* __restrict__ W_enc,
                        const float* __restrict__ b_enc,
                        const float* __restrict__ W_dec,
                        const float* __restrict__ b_dec,
                        const float* __restrict__ ecs_p,
                        const float* __restrict__ ep_p,
                        float* __restrict__ out,
                        int n_rows)
{
    __shared__ float sRed[8 * 32];   // per-warp: [0..23]=proj partials, [24]=ss, [25]=oss

    const int t    = threadIdx.x;
    const int wid  = t >> 5;
    const int lane = t & 31;
    const int c0   = t * CPT;

    // ---- prologue: BOTH weight slices into registers (no weight smem at all) ----
    float we[L_DIM][4];                  // W_enc[l][c0..c0+3] — 96 regs
    #pragma unroll
    for (int l = 0; l < L_DIM; ++l) {
        float4 v = *reinterpret_cast<const float4*>(&W_enc[l * D_DIM + c0]);
        we[l][0] = v.x; we[l][1] = v.y; we[l][2] = v.z; we[l][3] = v.w;
    }
    float wd[CPT][L_DIM];                // W_dec[c0+j][l] — 96 regs
    #pragma unroll
    for (int j = 0; j < CPT; ++j) {
        #pragma unroll
        for (int l = 0; l < L_DIM; l += 4) {
            float4 v = *reinterpret_cast<const float4*>(&W_dec[(c0 + j) * L_DIM + l]);
            wd[j][l + 0] = v.x; wd[j][l + 1] = v.y;
            wd[j][l + 2] = v.z; wd[j][l + 3] = v.w;
        }
    }
    const float4 bd  = *reinterpret_cast<const float4*>(&b_dec[c0]);
    const float  ecs = ecs_p[0];
    const float  ep  = ep_p[0];
    const float  benc = (lane < L_DIM) ? b_enc[lane] : 0.0f;   // every warp

    // split-butterfly final lane -> value-id map (lanes with (lane&3)==3 hold dups)
    const bool dup = ((lane & 3) == 3);
    const int  vid = 12 * ((lane >> 4) & 1) + 6 * ((lane >> 3) & 1)
                   + 3 * ((lane >> 2) & 1) + ((lane & 2) ? 2 : (lane & 1));

    int row = blockIdx.x;
    const int stride = gridDim.x;

    float4 dv = make_float4(0.f, 0.f, 0.f, 0.f);
    if (row < n_rows)
        dv = *reinterpret_cast<const float4*>(&data[(size_t)row * D_DIM + c0]);

    for (; row < n_rows; row += stride) {
        // ---- encode: weights from registers, zero LDS ----
        float ss = dv.x * dv.x + dv.y * dv.y + dv.z * dv.z + dv.w * dv.w;
        float acc[L_DIM];
        #pragma unroll
        for (int l = 0; l < L_DIM; ++l) {
            float a = dv.x * we[l][0];
            a = fmaf(dv.y, we[l][1], a);
            a = fmaf(dv.z, we[l][2], a);
            a = fmaf(dv.w, we[l][3], a);
            acc[l] = a;
        }

        // prefetch next row (dv dead after encode — issue now, consumed next iter)
        const int nrow = row + stride;
        float4 dnext = make_float4(0.f, 0.f, 0.f, 0.f);
        if (nrow < n_rows)
            dnext = *reinterpret_cast<const float4*>(&data[(size_t)nrow * D_DIM + c0]);

        // ---- value-split butterfly: same xor tree as naive, 5x fewer shuffles ----
        float w12[12];
        #pragma unroll
        for (int i = 0; i < 12; ++i) {
            float don = (lane & 16) ? acc[i] : acc[i + 12];
            float rec = __shfl_xor_sync(FULL, don, 16);
            w12[i] = ((lane & 16) ? acc[i + 12] : acc[i]) + rec;
        }
        float w6[6];
        #pragma unroll
        for (int i = 0; i < 6; ++i) {
            float don = (lane & 8) ? w12[i] : w12[i + 6];
            float rec = __shfl_xor_sync(FULL, don, 8);
            w6[i] = ((lane & 8) ? w12[i + 6] : w12[i]) + rec;
        }
        float w3[3];
        #pragma unroll
        for (int i = 0; i < 3; ++i) {
            float don = (lane & 4) ? w6[i] : w6[i + 3];
            float rec = __shfl_xor_sync(FULL, don, 4);
            w3[i] = ((lane & 4) ? w6[i + 3] : w6[i]) + rec;
        }
        float don4 = (lane & 2) ? w3[0] : w3[2];
        float rec4 = __shfl_xor_sync(FULL, don4, 2);
        float n0 = ((lane & 2) ? w3[2] : w3[0]) + rec4;
        float n1 = w3[1] + __shfl_xor_sync(FULL, w3[1], 2);
        float don5 = (lane & 1) ? n0 : n1;
        float rec5 = __shfl_xor_sync(FULL, don5, 1);
        float fin = ((lane & 1) ? n1 : n0) + rec5;

        #pragma unroll
        for (int off = 16; off > 0; off >>= 1)
            ss += __shfl_xor_sync(FULL, ss, off);

        if (!dup)      sRed[wid * 32 + vid] = fin;
        if (lane == 3) sRed[wid * 32 + 24]  = ss;
        __syncthreads();                                    // barrier A

        // ---- lattice math: EVERY warp computes it redundantly (bitwise identical) ----
        float s = 0.0f;
        if (lane <= L_DIM) {
            #pragma unroll
            for (int w = 0; w < TPB / 32; ++w)
                s += sRed[w * 32 + lane];
        }
        const float sumsq = __shfl_sync(FULL, s, L_DIM);
        const float in_e  = sqrtf(sumsq);

        float lp = 0.0f;
        if (lane < L_DIM)
            lp = rintf((s + benc) / ecs) * ecs;             // exact div + half-even round
        float q = lp * lp;                                  // lanes >= 24 contribute 0
        #pragma unroll
        for (int off = 16; off > 0; off >>= 1)
            q += __shfl_xor_sync(FULL, q, off);
        const float out_e = sqrtf(q);

        const float s1    = in_e / (out_e + EPSV) * ep;
        const float lat   = lp * s1;
        const float cor   = (fabsf(lat) > ecs) ? lat : 0.0f;
        const float in_e2 = fabsf(s1) * out_e;              // ||lattice||

        // ---- decode: weights from registers, cor via warp shuffle ----
        float r0 = bd.x, r1 = bd.y, r2 = bd.z, r3 = bd.w;
        #pragma unroll
        for (int l = 0; l < L_DIM; ++l) {
            const float c = __shfl_sync(FULL, cor, l);
            r0 = fmaf(c, wd[0][l], r0);
            r1 = fmaf(c, wd[1][l], r1);
            r2 = fmaf(c, wd[2][l], r2);
            r3 = fmaf(c, wd[3][l], r3);
        }

        // ---- out_e2 reduction ----
        float oss = r0 * r0 + r1 * r1 + r2 * r2 + r3 * r3;
        #pragma unroll
        for (int off = 16; off > 0; off >>= 1)
            oss += __shfl_xor_sync(FULL, oss, off);
        if (lane == 0) sRed[wid * 32 + 25] = oss;
        __syncthreads();                                    // barrier C

        float oe2 = 0.0f;
        #pragma unroll
        for (int w = 0; w < TPB / 32; ++w)
            oe2 += sRed[w * 32 + 25];

        const float s2 = in_e2 / (sqrtf(oe2) + EPSV) * ep;

        float4 o;
        o.x = r0 * s2; o.y = r1 * s2; o.z = r2 * s2; o.w = r3 * s2;
        *reinterpret_cast<float4*>(&out[(size_t)row * D_DIM + c0]) = o;

        dv = dnext;
    }
}

extern "C" void kernel_launch(void* const* d_in, const int* in_sizes, int n_in,
                              void* d_out, int out_size)
{
    const float* data  = (const float*)d_in[0];
    const float* W_enc = (const float*)d_in[1];
    const float* b_enc = (const float*)d_in[2];
    const float* W_dec = (const float*)d_in[3];
    const float* b_dec = (const float*)d_in[4];
    const float* ecs   = (const float*)d_in[5];
    const float* ep    = (const float*)d_in[6];
    float* out = (float*)d_out;

    const int n_rows = in_sizes[0] / D_DIM;   // 32768

    int dev = 0;
    cudaGetDevice(&dev);
    int sms = 0;
    cudaDeviceGetAttribute(&sms, cudaDevAttrMultiProcessorCount, dev);
    if (sms <= 0) sms = 148;

    leech_fused_kernel<<<sms, TPB>>>(data, W_enc, b_enc, W_dec, b_dec,
                                     ecs, ep, out, n_rows);
}